// round 1
// baseline (speedup 1.0000x reference)
#include <cuda_runtime.h>

#define Bb     8
#define Nn     3136
#define Cc     64
#define CI     32
#define BNROWS 25088          // Bb * Nn
#define LAMF   0.1f
#define HSTEP  0.05f
#define BNEPS  1e-3f

// ---- scratch (static device globals; no allocation) ----
__device__ float d_theta[BNROWS * CI];   // [B*N, 32]
__device__ float d_phi[BNROWS * CI];     // [B*N, 32]
__device__ float d_s[BNROWS];            // f_sum per row (lambda included)
__device__ float d_phisum[Bb * CI];      // per-batch sum of phi
__device__ float d_M[Bb * CI * Cc];      // per-batch phi^T @ g  [32,64]
__device__ float d_g1[BNROWS * Cc];      // g after iteration 0

// ---------------------------------------------------------------------------
// zero scratch accumulators
__global__ void k_zero_init() {
    int i = blockIdx.x * blockDim.x + threadIdx.x;
    if (i < Bb * CI) d_phisum[i] = 0.f;
    if (i < Bb * CI * Cc) d_M[i] = 0.f;
}
__global__ void k_zeroM() {
    int i = blockIdx.x * blockDim.x + threadIdx.x;
    if (i < Bb * CI * Cc) d_M[i] = 0.f;
}

// ---------------------------------------------------------------------------
// theta/phi = x @ Wt/Wp + bias ; also accumulate per-batch phi sum.
// 8 rows per 256-thread block (one warp per row, lane = output dim d).
__global__ void k_theta_phi(const float* __restrict__ x,
                            const float* __restrict__ Wt, const float* __restrict__ bt,
                            const float* __restrict__ Wp, const float* __restrict__ bp) {
    __shared__ float sx[8 * 64];
    __shared__ float sp[32];
    int tid = threadIdx.x;
    int r0  = blockIdx.x * 8;
    for (int i = tid; i < 8 * 64; i += 256) sx[i] = x[r0 * 64 + i];
    if (tid < 32) sp[tid] = 0.f;
    __syncthreads();

    int w = tid >> 5, d = tid & 31;
    float th = bt[d], ph = bp[d];
#pragma unroll
    for (int k = 0; k < 64; k++) {
        float xv = sx[w * 64 + k];
        th = fmaf(xv, Wt[k * 32 + d], th);
        ph = fmaf(xv, Wp[k * 32 + d], ph);
    }
    int r = r0 + w;
    d_theta[r * 32 + d] = th;
    d_phi[r * 32 + d]   = ph;
    atomicAdd(&sp[d], ph);
    __syncthreads();
    if (tid < 32) {
        int b = r0 / Nn;   // 3136 % 8 == 0, block never crosses batch
        atomicAdd(&d_phisum[b * 32 + tid], sp[tid]);
    }
}

// ---------------------------------------------------------------------------
// s[r] = LAM * dot(theta[r], phi_sum[batch(r)])   (== f_sum, iter-invariant)
__global__ void k_s() {
    int r = blockIdx.x * blockDim.x + threadIdx.x;
    if (r >= BNROWS) return;
    int b = r / Nn;
    float acc = 0.f;
#pragma unroll
    for (int d = 0; d < 32; d++)
        acc = fmaf(d_theta[r * 32 + d], d_phisum[b * 32 + d], acc);
    d_s[r] = LAMF * acc;
}

// ---------------------------------------------------------------------------
// M[b] = phi[b]^T @ g[b]   ([32,64], K-reduction over N=3136)
// grid = 8 batches * 56 chunks; each block reduces 56 rows (7 tiles of 8),
// each thread owns 8 accumulators (d = tid&31, c in [cb, cb+8)).
__global__ void k_reduceM(const float* __restrict__ x, int use_g1) {
    const float* g = use_g1 ? d_g1 : x;
    __shared__ float sph[8 * 32];
    __shared__ float sg[8 * 64];
    int tid   = threadIdx.x;
    int b     = blockIdx.x / 56;
    int chunk = blockIdx.x % 56;
    int d  = tid & 31;
    int cb = (tid >> 5) * 8;
    float acc[8] = {0.f, 0.f, 0.f, 0.f, 0.f, 0.f, 0.f, 0.f};

    for (int t = 0; t < 7; t++) {
        int row0 = b * Nn + chunk * 56 + t * 8;
        sph[tid]      = d_phi[row0 * 32 + tid];
        sg[tid]       = g[row0 * 64 + tid];
        sg[tid + 256] = g[row0 * 64 + tid + 256];
        __syncthreads();
#pragma unroll
        for (int j = 0; j < 8; j++) {
            float pd = sph[j * 32 + d];
#pragma unroll
            for (int q = 0; q < 8; q++)
                acc[q] = fmaf(pd, sg[j * 64 + cb + q], acc[q]);
        }
        __syncthreads();
    }
    float* Mb = &d_M[b * 2048 + d * 64 + cb];
#pragma unroll
    for (int q = 0; q < 8; q++) atomicAdd(&Mb[q], acc[q]);
}

// ---------------------------------------------------------------------------
// Fused per-row epilogue:
//   fg = (LAM * theta_row @ M  -  g_row * s) / N
//   o  = fg @ W[iter] + b[iter];  BN(inference);  ReLU;  out = x + 0.05*o
// 4 rows per 256-thread block (64 threads per row, thread = channel c).
__global__ void k_apply(const float* __restrict__ x,
                        const float* __restrict__ Wst, const float* __restrict__ bst,
                        const float* __restrict__ gam, const float* __restrict__ bet,
                        const float* __restrict__ mmean, const float* __restrict__ mvar,
                        int iter, int gin_is_g1, float* __restrict__ out_ext, int out_is_g1) {
    const float* gin = gin_is_g1 ? d_g1 : x;
    float* out       = out_is_g1 ? d_g1 : out_ext;

    __shared__ float sW[64 * 64];
    __shared__ float sth[4 * 32];
    __shared__ float sfg[4 * 64];

    int tid = threadIdx.x;
    const float* Wi = Wst + iter * 64 * 64;
    for (int i = tid; i < 64 * 64; i += 256) sW[i] = Wi[i];
    int r0 = blockIdx.x * 4;
    if (tid < 128) sth[tid] = d_theta[r0 * 32 + tid];
    __syncthreads();

    int rg = tid >> 6, c = tid & 63;
    int r  = r0 + rg;
    int b  = r / Nn;   // 3136 % 4 == 0, block never crosses batch

    const float* Mb = &d_M[b * 2048 + c];
    float acc = 0.f;
#pragma unroll
    for (int d = 0; d < 32; d++)
        acc = fmaf(sth[rg * 32 + d], Mb[d * 64], acc);

    float fg = (LAMF * acc - gin[r * 64 + c] * d_s[r]) * (1.0f / (float)Nn);
    sfg[rg * 64 + c] = fg;
    __syncthreads();

    float o = bst[iter * 64 + c];
#pragma unroll
    for (int c2 = 0; c2 < 64; c2++)
        o = fmaf(sfg[rg * 64 + c2], sW[c2 * 64 + c], o);

    int ic = iter * 64 + c;
    o = (o - mmean[ic]) * gam[ic] * rsqrtf(mvar[ic] + BNEPS) + bet[ic];
    o = fmaxf(o, 0.f);
    out[r * 64 + c] = x[r * 64 + c] + HSTEP * o;   // last == x always
}

// ---------------------------------------------------------------------------
extern "C" void kernel_launch(void* const* d_in, const int* in_sizes, int n_in,
                              void* d_out, int out_size) {
    const float* x     = (const float*)d_in[0];
    const float* Wt    = (const float*)d_in[1];
    const float* bt    = (const float*)d_in[2];
    const float* Wp    = (const float*)d_in[3];
    const float* bp    = (const float*)d_in[4];
    const float* Wst   = (const float*)d_in[5];
    const float* bst   = (const float*)d_in[6];
    const float* gam   = (const float*)d_in[7];
    const float* bet   = (const float*)d_in[8];
    const float* mmean = (const float*)d_in[9];
    const float* mvar  = (const float*)d_in[10];
    float* out = (float*)d_out;

    k_zero_init<<<(Bb * CI * Cc + 255) / 256, 256>>>();
    k_theta_phi<<<BNROWS / 8, 256>>>(x, Wt, bt, Wp, bp);
    k_s<<<(BNROWS + 255) / 256, 256>>>();

    // iteration 0: g = x, write g1
    k_reduceM<<<Bb * 56, 256>>>(x, 0);
    k_apply<<<BNROWS / 4, 256>>>(x, Wst, bst, gam, bet, mmean, mvar, 0, 0, nullptr, 1);

    // iteration 1: g = g1, write d_out
    k_zeroM<<<(Bb * CI * Cc + 255) / 256, 256>>>();
    k_reduceM<<<Bb * 56, 256>>>(x, 1);
    k_apply<<<BNROWS / 4, 256>>>(x, Wst, bst, gam, bet, mmean, mvar, 1, 1, out, 0);
}

// round 2
// speedup vs baseline: 1.4106x; 1.4106x over previous
#include <cuda_runtime.h>

#define Bb     8
#define Nn     3136
#define Cc     64
#define CI     32
#define BNROWS 25088          // Bb * Nn
#define LAMF   0.1f
#define HSTEP  0.05f
#define BNEPS  1e-3f
#define INVN   (1.0f / 3136.0f)

// ---- scratch (static device globals; no allocation) ----
__device__ float d_theta[BNROWS * CI];
__device__ float d_phi[BNROWS * CI];
__device__ float d_phisum[Bb * CI];
__device__ float d_M[2][Bb * CI * Cc];   // double-buffered per iteration
__device__ float d_g1[BNROWS * Cc];

// ---------------------------------------------------------------------------
__global__ void k_zero() {
    int i = blockIdx.x * blockDim.x + threadIdx.x;
    if (i < Bb * CI) d_phisum[i] = 0.f;
    if (i < 2 * Bb * CI * Cc) ((float*)d_M)[i] = 0.f;
}

// ---------------------------------------------------------------------------
// theta/phi = x @ Wt/Wp + bias; accumulate per-batch phi sum.
// 32 rows/block, 8 warps * 4 rows, lane = output dim d. Weights staged in smem
// transposed [d][k] (pad 68) for float4 inner loop.
__global__ void __launch_bounds__(256) k_theta_phi(
        const float* __restrict__ x,
        const float* __restrict__ Wt, const float* __restrict__ bt,
        const float* __restrict__ Wp, const float* __restrict__ bp) {
    __shared__ float sx[32 * 64];
    __shared__ float sWt[32 * 68];
    __shared__ float sWp[32 * 68];
    __shared__ float sp[32];
    int t  = threadIdx.x;
    int r0 = blockIdx.x * 32;

    {   // x: 2048 floats = 512 float4
        const float4* src = (const float4*)(x + r0 * 64);
        float4* dst = (float4*)sx;
        dst[t] = src[t];
        dst[t + 256] = src[t + 256];
    }
    for (int e = t; e < 2048; e += 256) {   // weights transposed
        int k = e >> 5, d = e & 31;
        sWt[d * 68 + k] = Wt[e];
        sWp[d * 68 + k] = Wp[e];
    }
    if (t < 32) sp[t] = 0.f;
    __syncthreads();

    int w = t >> 5, d = t & 31;
    float th[4], ph[4];
    float bt_d = bt[d], bp_d = bp[d];
#pragma unroll
    for (int j = 0; j < 4; j++) { th[j] = bt_d; ph[j] = bp_d; }

    const float* xr = sx + w * 4 * 64;
    const float* wt = sWt + d * 68;
    const float* wp = sWp + d * 68;
#pragma unroll
    for (int k = 0; k < 64; k += 4) {
        float4 a = *(const float4*)(wt + k);
        float4 b = *(const float4*)(wp + k);
#pragma unroll
        for (int j = 0; j < 4; j++) {
            float4 xv = *(const float4*)(xr + j * 64 + k);
            th[j] = fmaf(xv.x, a.x, th[j]); th[j] = fmaf(xv.y, a.y, th[j]);
            th[j] = fmaf(xv.z, a.z, th[j]); th[j] = fmaf(xv.w, a.w, th[j]);
            ph[j] = fmaf(xv.x, b.x, ph[j]); ph[j] = fmaf(xv.y, b.y, ph[j]);
            ph[j] = fmaf(xv.z, b.z, ph[j]); ph[j] = fmaf(xv.w, b.w, ph[j]);
        }
    }
    int r = r0 + w * 4;
    float phs = 0.f;
#pragma unroll
    for (int j = 0; j < 4; j++) {
        d_theta[(r + j) * 32 + d] = th[j];
        d_phi[(r + j) * 32 + d]   = ph[j];
        phs += ph[j];
    }
    atomicAdd(&sp[d], phs);
    __syncthreads();
    if (t < 32) atomicAdd(&d_phisum[(r0 / Nn) * 32 + t], sp[t]);
}

// ---------------------------------------------------------------------------
// M[iter][b] += phi[b]^T @ g[b]. 64 rows/block, 4 double-buffered 16-row tiles.
__global__ void __launch_bounds__(256) k_reduceM(const float* __restrict__ x,
                                                 int use_g1, int iter) {
    const float* g = use_g1 ? d_g1 : x;
    __shared__ float sph[2][16 * 32];
    __shared__ float sg[2][16 * 64];
    int t     = threadIdx.x;
    int b     = blockIdx.x / 49;
    int chunk = blockIdx.x % 49;
    int row0  = b * Nn + chunk * 64;
    int d = t & 31, cb = (t >> 5) * 8;
    float acc[8] = {0.f, 0.f, 0.f, 0.f, 0.f, 0.f, 0.f, 0.f};

    const float4* phg = (const float4*)(d_phi + row0 * 32);  // 4 tiles * 128 f4
    const float4* gg  = (const float4*)(g + row0 * 64);      // 4 tiles * 256 f4

    if (t < 128) ((float4*)sph[0])[t] = phg[t];
    ((float4*)sg[0])[t] = gg[t];
    __syncthreads();

#pragma unroll
    for (int tt = 0; tt < 4; tt++) {
        int cur = tt & 1, nxt = cur ^ 1;
        float4 pre_p, pre_g;
        if (tt < 3) {
            if (t < 128) pre_p = phg[(tt + 1) * 128 + t];
            pre_g = gg[(tt + 1) * 256 + t];
        }
        const float* P = sph[cur];
        const float* G = sg[cur];
#pragma unroll
        for (int j = 0; j < 16; j++) {
            float pd = P[j * 32 + d];
            float4 g0 = *(const float4*)(G + j * 64 + cb);
            float4 g1 = *(const float4*)(G + j * 64 + cb + 4);
            acc[0] = fmaf(pd, g0.x, acc[0]); acc[1] = fmaf(pd, g0.y, acc[1]);
            acc[2] = fmaf(pd, g0.z, acc[2]); acc[3] = fmaf(pd, g0.w, acc[3]);
            acc[4] = fmaf(pd, g1.x, acc[4]); acc[5] = fmaf(pd, g1.y, acc[5]);
            acc[6] = fmaf(pd, g1.z, acc[6]); acc[7] = fmaf(pd, g1.w, acc[7]);
        }
        if (tt < 3) {
            if (t < 128) ((float4*)sph[nxt])[t] = pre_p;
            ((float4*)sg[nxt])[t] = pre_g;
        }
        __syncthreads();
    }
    float* Mb = d_M[iter] + b * 2048 + d * 64 + cb;
#pragma unroll
    for (int q = 0; q < 8; q++) atomicAdd(&Mb[q], acc[q]);
}

// ---------------------------------------------------------------------------
// Fused epilogue (incl. s = f_sum computation):
//   s   = LAM * theta_row . phisum[b]
//   fg  = (LAM * theta_row @ M - g_row * s) / N
//   o   = fg @ W[iter] + b[iter]; BN; ReLU; out = x + 0.05*o
// 32 rows/block, thread owns (c = t&63, rows rg+4j).
__global__ void __launch_bounds__(256) k_apply(
        const float* __restrict__ x,
        const float* __restrict__ Wst, const float* __restrict__ bst,
        const float* __restrict__ gam, const float* __restrict__ bet,
        const float* __restrict__ mmean, const float* __restrict__ mvar,
        int iter, int gin_is_g1, float* __restrict__ out_ext, int out_is_g1) {
    const float* gin = gin_is_g1 ? d_g1 : x;
    float* out       = out_is_g1 ? d_g1 : out_ext;

    __shared__ float sWc[64 * 68];   // W transposed: [c][c2], pad 68
    __shared__ float sMt[64 * 36];   // M transposed: [c][d],  pad 36
    __shared__ float sth[32 * 32];
    __shared__ float sfg[32 * 64];
    __shared__ float ss[32];

    int t  = threadIdx.x;
    int r0 = blockIdx.x * 32;
    int b  = r0 / Nn;

    const float* Wi = Wst + iter * 4096;
    const float* Mi = d_M[iter] + b * 2048;
    for (int e = t; e < 4096; e += 256) { int c2 = e >> 6, c = e & 63; sWc[c * 68 + c2] = Wi[e]; }
    for (int e = t; e < 2048; e += 256) { int dd = e >> 6, c = e & 63; sMt[c * 36 + dd] = Mi[e]; }
    { ((float4*)sth)[t] = ((const float4*)(d_theta + r0 * 32))[t]; }
    __syncthreads();

    if (t < 32) {   // s per row (f_sum, lambda included)
        float a = 0.f;
        const float* thr = sth + t * 32;
        const float* ps  = d_phisum + b * 32;
#pragma unroll
        for (int dd = 0; dd < 32; dd++) a = fmaf(thr[dd], ps[dd], a);
        ss[t] = LAMF * a;
    }
    __syncthreads();

    int c = t & 63, rg = t >> 6;   // rows rg, rg+4, ..., rg+28

    // phase 1: fg = theta @ M
    float fg[8] = {0.f, 0.f, 0.f, 0.f, 0.f, 0.f, 0.f, 0.f};
    const float* mc = sMt + c * 36;
#pragma unroll
    for (int dd = 0; dd < 32; dd += 4) {
        float4 m = *(const float4*)(mc + dd);
#pragma unroll
        for (int j = 0; j < 8; j++) {
            float4 tv = *(const float4*)(sth + (rg + 4 * j) * 32 + dd);
            fg[j] = fmaf(tv.x, m.x, fg[j]); fg[j] = fmaf(tv.y, m.y, fg[j]);
            fg[j] = fmaf(tv.z, m.z, fg[j]); fg[j] = fmaf(tv.w, m.w, fg[j]);
        }
    }
#pragma unroll
    for (int j = 0; j < 8; j++) {
        int r = rg + 4 * j;
        fg[j] = (LAMF * fg[j] - gin[(r0 + r) * 64 + c] * ss[r]) * INVN;
        sfg[r * 64 + c] = fg[j];
    }
    __syncthreads();

    // phase 2: o = fg @ W + bias
    float o[8];
    float bias = bst[iter * 64 + c];
#pragma unroll
    for (int j = 0; j < 8; j++) o[j] = bias;
    const float* wc = sWc + c * 68;
#pragma unroll
    for (int c2 = 0; c2 < 64; c2 += 4) {
        float4 wv = *(const float4*)(wc + c2);
#pragma unroll
        for (int j = 0; j < 8; j++) {
            float4 fv = *(const float4*)(sfg + (rg + 4 * j) * 64 + c2);
            o[j] = fmaf(fv.x, wv.x, o[j]); o[j] = fmaf(fv.y, wv.y, o[j]);
            o[j] = fmaf(fv.z, wv.z, o[j]); o[j] = fmaf(fv.w, wv.w, o[j]);
        }
    }
    int ic = iter * 64 + c;
    float scale = gam[ic] * rsqrtf(mvar[ic] + BNEPS);
    float mean = mmean[ic], beta_c = bet[ic];
#pragma unroll
    for (int j = 0; j < 8; j++) {
        int r = r0 + rg + 4 * j;
        float oo = (o[j] - mean) * scale + beta_c;
        oo = fmaxf(oo, 0.f);
        out[r * 64 + c] = x[r * 64 + c] + HSTEP * oo;   // last == x always
    }
}

// ---------------------------------------------------------------------------
extern "C" void kernel_launch(void* const* d_in, const int* in_sizes, int n_in,
                              void* d_out, int out_size) {
    const float* x     = (const float*)d_in[0];
    const float* Wt    = (const float*)d_in[1];
    const float* bt    = (const float*)d_in[2];
    const float* Wp    = (const float*)d_in[3];
    const float* bp    = (const float*)d_in[4];
    const float* Wst   = (const float*)d_in[5];
    const float* bst   = (const float*)d_in[6];
    const float* gam   = (const float*)d_in[7];
    const float* bet   = (const float*)d_in[8];
    const float* mmean = (const float*)d_in[9];
    const float* mvar  = (const float*)d_in[10];
    float* out = (float*)d_out;

    k_zero<<<128, 256>>>();
    k_theta_phi<<<BNROWS / 32, 256>>>(x, Wt, bt, Wp, bp);

    // iteration 0: g = x, write g1
    k_reduceM<<<Bb * 49, 256>>>(x, 0, 0);
    k_apply<<<BNROWS / 32, 256>>>(x, Wst, bst, gam, bet, mmean, mvar, 0, 0, nullptr, 1);

    // iteration 1: g = g1, write d_out
    k_reduceM<<<Bb * 49, 256>>>(x, 1, 1);
    k_apply<<<BNROWS / 32, 256>>>(x, Wst, bst, gam, bet, mmean, mvar, 1, 1, out, 0);
}

// round 3
// speedup vs baseline: 1.5220x; 1.0790x over previous
#include <cuda_runtime.h>

#define Bb     8
#define Nn     3136
#define Cc     64
#define CI     32
#define BNROWS 25088          // Bb * Nn
#define LAMF   0.1f
#define HSTEP  0.05f
#define BNEPS  1e-3f
#define INVN   (1.0f / 3136.0f)

// ---- scratch (static device globals; no allocation) ----
__device__ float d_theta[BNROWS * CI];
__device__ float d_phi[BNROWS * CI];
__device__ float d_phisum[Bb * CI];
__device__ float d_M[2][Bb * CI * Cc];      // per-iteration phi^T g
__device__ float d_MW[2][Bb * CI * Cc];     // (lam/N) * M @ W[iter]
__device__ float d_g1[BNROWS * Cc];

// ---------------------------------------------------------------------------
__global__ void k_zero() {
    int i = blockIdx.x * blockDim.x + threadIdx.x;
    if (i < Bb * CI) d_phisum[i] = 0.f;
    if (i < 2 * Bb * CI * Cc) ((float*)d_M)[i] = 0.f;
}

// ---------------------------------------------------------------------------
// theta/phi = x @ Wt/Wp + bias; accumulate per-batch phi sum.
__global__ void __launch_bounds__(256) k_theta_phi(
        const float* __restrict__ x,
        const float* __restrict__ Wt, const float* __restrict__ bt,
        const float* __restrict__ Wp, const float* __restrict__ bp) {
    __shared__ float sx[32 * 64];
    __shared__ float sWt[32 * 68];
    __shared__ float sWp[32 * 68];
    __shared__ float sp[32];
    int t  = threadIdx.x;
    int r0 = blockIdx.x * 32;

    {
        const float4* src = (const float4*)(x + r0 * 64);
        float4* dst = (float4*)sx;
        dst[t] = src[t];
        dst[t + 256] = src[t + 256];
    }
    for (int e = t; e < 2048; e += 256) {   // weights transposed
        int k = e >> 5, d = e & 31;
        sWt[d * 68 + k] = Wt[e];
        sWp[d * 68 + k] = Wp[e];
    }
    if (t < 32) sp[t] = 0.f;
    __syncthreads();

    int w = t >> 5, d = t & 31;
    float th[4], ph[4];
    float bt_d = bt[d], bp_d = bp[d];
#pragma unroll
    for (int j = 0; j < 4; j++) { th[j] = bt_d; ph[j] = bp_d; }

    const float* xr = sx + w * 4 * 64;
    const float* wt = sWt + d * 68;
    const float* wp = sWp + d * 68;
#pragma unroll
    for (int k = 0; k < 64; k += 4) {
        float4 a = *(const float4*)(wt + k);
        float4 b = *(const float4*)(wp + k);
#pragma unroll
        for (int j = 0; j < 4; j++) {
            float4 xv = *(const float4*)(xr + j * 64 + k);
            th[j] = fmaf(xv.x, a.x, th[j]); th[j] = fmaf(xv.y, a.y, th[j]);
            th[j] = fmaf(xv.z, a.z, th[j]); th[j] = fmaf(xv.w, a.w, th[j]);
            ph[j] = fmaf(xv.x, b.x, ph[j]); ph[j] = fmaf(xv.y, b.y, ph[j]);
            ph[j] = fmaf(xv.z, b.z, ph[j]); ph[j] = fmaf(xv.w, b.w, ph[j]);
        }
    }
    int r = r0 + w * 4;
    float phs = 0.f;
#pragma unroll
    for (int j = 0; j < 4; j++) {
        d_theta[(r + j) * 32 + d] = th[j];
        d_phi[(r + j) * 32 + d]   = ph[j];
        phs += ph[j];
    }
    atomicAdd(&sp[d], phs);
    __syncthreads();
    if (t < 32) atomicAdd(&d_phisum[(r0 / Nn) * 32 + t], sp[t]);
}

// ---------------------------------------------------------------------------
// M[iter][b] += phi[b]^T @ g[b]. 64 rows/block, 4 double-buffered 16-row tiles.
__global__ void __launch_bounds__(256) k_reduceM(const float* __restrict__ x,
                                                 int use_g1, int iter) {
    const float* g = use_g1 ? d_g1 : x;
    __shared__ float sph[2][16 * 32];
    __shared__ float sg[2][16 * 64];
    int t     = threadIdx.x;
    int b     = blockIdx.x / 49;
    int chunk = blockIdx.x % 49;
    int row0  = b * Nn + chunk * 64;
    int d = t & 31, cb = (t >> 5) * 8;
    float acc[8] = {0.f, 0.f, 0.f, 0.f, 0.f, 0.f, 0.f, 0.f};

    const float4* phg = (const float4*)(d_phi + row0 * 32);
    const float4* gg  = (const float4*)(g + row0 * 64);

    if (t < 128) ((float4*)sph[0])[t] = phg[t];
    ((float4*)sg[0])[t] = gg[t];
    __syncthreads();

#pragma unroll
    for (int tt = 0; tt < 4; tt++) {
        int cur = tt & 1, nxt = cur ^ 1;
        float4 pre_p, pre_g;
        if (tt < 3) {
            if (t < 128) pre_p = phg[(tt + 1) * 128 + t];
            pre_g = gg[(tt + 1) * 256 + t];
        }
        const float* P = sph[cur];
        const float* G = sg[cur];
#pragma unroll
        for (int j = 0; j < 16; j++) {
            float pd = P[j * 32 + d];
            float4 g0 = *(const float4*)(G + j * 64 + cb);
            float4 g1 = *(const float4*)(G + j * 64 + cb + 4);
            acc[0] = fmaf(pd, g0.x, acc[0]); acc[1] = fmaf(pd, g0.y, acc[1]);
            acc[2] = fmaf(pd, g0.z, acc[2]); acc[3] = fmaf(pd, g0.w, acc[3]);
            acc[4] = fmaf(pd, g1.x, acc[4]); acc[5] = fmaf(pd, g1.y, acc[5]);
            acc[6] = fmaf(pd, g1.z, acc[6]); acc[7] = fmaf(pd, g1.w, acc[7]);
        }
        if (tt < 3) {
            if (t < 128) ((float4*)sph[nxt])[t] = pre_p;
            ((float4*)sg[nxt])[t] = pre_g;
        }
        __syncthreads();
    }
    float* Mb = d_M[iter] + b * 2048 + d * 64 + cb;
#pragma unroll
    for (int q = 0; q < 8; q++) atomicAdd(&Mb[q], acc[q]);
}

// ---------------------------------------------------------------------------
// MW[iter][b] = (LAM/N) * M[iter][b] @ W[iter]   ([32,64] @ [64,64])
__global__ void __launch_bounds__(256) k_mw(const float* __restrict__ Wst, int iter) {
    __shared__ float sM[32 * 64];
    __shared__ float sW[64 * 68];
    int t = threadIdx.x;
    int b = blockIdx.x;
    const float* Mi = d_M[iter] + b * 2048;
    const float* Wi = Wst + iter * 4096;

    ((float4*)sM)[t] = ((const float4*)Mi)[t];
    ((float4*)sM)[t + 256] = ((const float4*)Mi)[t + 256];
    for (int e = t; e < 1024; e += 256) {
        int k = e >> 4, c4 = (e & 15) * 4;
        *(float4*)(sW + k * 68 + c4) = ((const float4*)Wi)[e];
    }
    __syncthreads();

    int d = t >> 3, c0 = (t & 7) * 8;
    float acc[8] = {0.f, 0.f, 0.f, 0.f, 0.f, 0.f, 0.f, 0.f};
#pragma unroll 8
    for (int c = 0; c < 64; c++) {
        float m = sM[d * 64 + c];
        float4 w0 = *(const float4*)(sW + c * 68 + c0);
        float4 w1 = *(const float4*)(sW + c * 68 + c0 + 4);
        acc[0] = fmaf(m, w0.x, acc[0]); acc[1] = fmaf(m, w0.y, acc[1]);
        acc[2] = fmaf(m, w0.z, acc[2]); acc[3] = fmaf(m, w0.w, acc[3]);
        acc[4] = fmaf(m, w1.x, acc[4]); acc[5] = fmaf(m, w1.y, acc[5]);
        acc[6] = fmaf(m, w1.z, acc[6]); acc[7] = fmaf(m, w1.w, acc[7]);
    }
    float* o = d_MW[iter] + b * 2048 + d * 64 + c0;
    const float sc = LAMF * INVN;
#pragma unroll
    for (int q = 0; q < 8; q++) o[q] = sc * acc[q];
}

// ---------------------------------------------------------------------------
// Single K=96 GEMM epilogue:  o = [theta | -(s/N) g] @ [MW ; W] + bias; BN; ReLU;
// out = x + 0.05*o.  64 rows/block (3136 = 64*49, never crosses batch),
// 4x4 register tile per thread.
__global__ void __launch_bounds__(256) k_apply(
        const float* __restrict__ x,
        const float* __restrict__ Wst, const float* __restrict__ bst,
        const float* __restrict__ gam, const float* __restrict__ bet,
        const float* __restrict__ mmean, const float* __restrict__ mvar,
        int iter, int gin_is_g1, float* __restrict__ out_ext, int out_is_g1) {
    const float* gin = gin_is_g1 ? d_g1 : x;
    float* out       = out_is_g1 ? d_g1 : out_ext;

    __shared__ float sAt[96 * 68];   // A transposed: [k][row], pad 68
    __shared__ float sB[96 * 68];    // B: [k][col], pad 68
    __shared__ float ss[64];
    __shared__ float sps[32];

    int t  = threadIdx.x;
    int r0 = blockIdx.x * 64;
    int b  = blockIdx.x / 49;

    // stage theta -> sAt rows [0,32)
#pragma unroll
    for (int j = 0; j < 2; j++) {
        int e = t + j * 256;                    // 512 float4
        int r = e >> 3, dd = (e & 7) * 4;
        float4 v = ((const float4*)(d_theta + r0 * 32))[e];
        sAt[(dd + 0) * 68 + r] = v.x;
        sAt[(dd + 1) * 68 + r] = v.y;
        sAt[(dd + 2) * 68 + r] = v.z;
        sAt[(dd + 3) * 68 + r] = v.w;
    }
    // stage B: rows [0,32) = MW (pre-scaled by lam/N), rows [32,96) = W
    const float* MWi = d_MW[iter] + b * 2048;
    const float* Wi  = Wst + iter * 4096;
#pragma unroll
    for (int j = 0; j < 6; j++) {
        int e = t + j * 256;                    // 1536 float4
        if (e < 512) {
            int k = e >> 4, c4 = (e & 15) * 4;
            *(float4*)(sB + k * 68 + c4) = ((const float4*)MWi)[e];
        } else {
            int e2 = e - 512;
            int k = e2 >> 4, c4 = (e2 & 15) * 4;
            *(float4*)(sB + (32 + k) * 68 + c4) = ((const float4*)Wi)[e2];
        }
    }
    if (t < 32) sps[t] = d_phisum[b * 32 + t];
    __syncthreads();

    // s per row
    if (t < 64) {
        float a = 0.f;
#pragma unroll
        for (int k = 0; k < 32; k++) a = fmaf(sAt[k * 68 + t], sps[k], a);
        ss[t] = a * (-LAMF * INVN);             // -(s/N), s = LAM * theta.phisum
    }
    __syncthreads();

    // stage scaled g -> sAt rows [32,96)
#pragma unroll
    for (int j = 0; j < 4; j++) {
        int e = t + j * 256;                    // 1024 float4
        int r = e >> 4, c4 = (e & 15) * 4;
        float4 v = ((const float4*)(gin + r0 * 64))[e];
        float sc = ss[r];
        sAt[(32 + c4 + 0) * 68 + r] = v.x * sc;
        sAt[(32 + c4 + 1) * 68 + r] = v.y * sc;
        sAt[(32 + c4 + 2) * 68 + r] = v.z * sc;
        sAt[(32 + c4 + 3) * 68 + r] = v.w * sc;
    }
    __syncthreads();

    // GEMM: 4x4 register tile.  tx in [0,16) -> cols, ty in [0,16) -> rows
    int tx = t & 15, ty = t >> 4;
    int rr = ty * 4, cc = tx * 4;
    float acc[4][4];
#pragma unroll
    for (int i = 0; i < 4; i++)
#pragma unroll
        for (int j = 0; j < 4; j++) acc[i][j] = 0.f;

#pragma unroll 8
    for (int k = 0; k < 96; k++) {
        float4 a = *(const float4*)(sAt + k * 68 + rr);
        float4 bv = *(const float4*)(sB + k * 68 + cc);
        acc[0][0] = fmaf(a.x, bv.x, acc[0][0]); acc[0][1] = fmaf(a.x, bv.y, acc[0][1]);
        acc[0][2] = fmaf(a.x, bv.z, acc[0][2]); acc[0][3] = fmaf(a.x, bv.w, acc[0][3]);
        acc[1][0] = fmaf(a.y, bv.x, acc[1][0]); acc[1][1] = fmaf(a.y, bv.y, acc[1][1]);
        acc[1][2] = fmaf(a.y, bv.z, acc[1][2]); acc[1][3] = fmaf(a.y, bv.w, acc[1][3]);
        acc[2][0] = fmaf(a.z, bv.x, acc[2][0]); acc[2][1] = fmaf(a.z, bv.y, acc[2][1]);
        acc[2][2] = fmaf(a.z, bv.z, acc[2][2]); acc[2][3] = fmaf(a.z, bv.w, acc[2][3]);
        acc[3][0] = fmaf(a.w, bv.x, acc[3][0]); acc[3][1] = fmaf(a.w, bv.y, acc[3][1]);
        acc[3][2] = fmaf(a.w, bv.z, acc[3][2]); acc[3][3] = fmaf(a.w, bv.w, acc[3][3]);
    }

    // epilogue: bias, BN, ReLU, residual
    float4 bias = *(const float4*)(bst + iter * 64 + cc);
    float4 gm   = *(const float4*)(gam + iter * 64 + cc);
    float4 bt4  = *(const float4*)(bet + iter * 64 + cc);
    float4 mm   = *(const float4*)(mmean + iter * 64 + cc);
    float4 mv   = *(const float4*)(mvar + iter * 64 + cc);
    float scl[4] = { gm.x * rsqrtf(mv.x + BNEPS), gm.y * rsqrtf(mv.y + BNEPS),
                     gm.z * rsqrtf(mv.z + BNEPS), gm.w * rsqrtf(mv.w + BNEPS) };
    float bia[4] = { bias.x, bias.y, bias.z, bias.w };
    float mean[4] = { mm.x, mm.y, mm.z, mm.w };
    float betc[4] = { bt4.x, bt4.y, bt4.z, bt4.w };

#pragma unroll
    for (int i = 0; i < 4; i++) {
        int r = r0 + rr + i;
        float4 xv = *(const float4*)(x + r * 64 + cc);
        float xa[4] = { xv.x, xv.y, xv.z, xv.w };
        float4 ov;
        float* op = (float*)&ov;
#pragma unroll
        for (int j = 0; j < 4; j++) {
            float o = acc[i][j] + bia[j];
            o = (o - mean[j]) * scl[j] + betc[j];
            o = fmaxf(o, 0.f);
            op[j] = xa[j] + HSTEP * o;
        }
        *(float4*)(out + r * 64 + cc) = ov;
    }
}

// ---------------------------------------------------------------------------
extern "C" void kernel_launch(void* const* d_in, const int* in_sizes, int n_in,
                              void* d_out, int out_size) {
    const float* x     = (const float*)d_in[0];
    const float* Wt    = (const float*)d_in[1];
    const float* bt    = (const float*)d_in[2];
    const float* Wp    = (const float*)d_in[3];
    const float* bp    = (const float*)d_in[4];
    const float* Wst   = (const float*)d_in[5];
    const float* bst   = (const float*)d_in[6];
    const float* gam   = (const float*)d_in[7];
    const float* bet   = (const float*)d_in[8];
    const float* mmean = (const float*)d_in[9];
    const float* mvar  = (const float*)d_in[10];
    float* out = (float*)d_out;

    k_zero<<<128, 256>>>();
    k_theta_phi<<<BNROWS / 32, 256>>>(x, Wt, bt, Wp, bp);

    // iteration 0: g = x, write g1
    k_reduceM<<<Bb * 49, 256>>>(x, 0, 0);
    k_mw<<<Bb, 256>>>(Wst, 0);
    k_apply<<<BNROWS / 64, 256>>>(x, Wst, bst, gam, bet, mmean, mvar, 0, 0, nullptr, 1);

    // iteration 1: g = g1, write d_out
    k_reduceM<<<Bb * 49, 256>>>(x, 1, 1);
    k_mw<<<Bb, 256>>>(Wst, 1);
    k_apply<<<BNROWS / 64, 256>>>(x, Wst, bst, gam, bet, mmean, mvar, 1, 1, out, 0);
}